// round 12
// baseline (speedup 1.0000x reference)
#include <cuda_runtime.h>
#include <cstdint>

#define RES      64
#define N_PHAL   20
#define MAX_B    256

constexpr int POS_PER_CHUNK = RES * RES;             // 4096 positions per (b,p)
constexpr int F4_PER_CHUNK  = POS_PER_CHUNK * 5 / 4; // 5120 float4s per chunk
constexpr int TILE_POS      = 2048;                  // positions per smem tile
constexpr int TILE_F4       = TILE_POS * 5 / 4;      // 2560 float4s = 40 KB
constexpr int THREADS       = 256;

// Scratch: per (b,p): vf0, vf1, vs0, vs1, den
__device__ float        g_scratch[MAX_B * N_PHAL * 5];
__device__ unsigned int g_count = 0;

__device__ __forceinline__ float warp_red(float v) {
    #pragma unroll
    for (int o = 16; o > 0; o >>= 1)
        v += __shfl_down_sync(0xffffffffu, v, o);
    return v;
}

// One block per (b, phal) chunk: stream 80 KB through SMEM, reduce 7 sums.
// __launch_bounds__(256, 5): cap regs at 48 so 5 CTAs/SM co-reside (the R2
// engine's occupancy) — spills, if any, land in the cold finalize branch.
__global__ __launch_bounds__(THREADS, 5) void fused_kernel(
    const float4* __restrict__ x, float* __restrict__ scratch,
    float* __restrict__ out, int total_chunks)
{
    __shared__ float4 tile[TILE_F4];     // 40 KB
    __shared__ float  red[8][7];
    __shared__ int    s_last;

    const int chunk = blockIdx.x;        // b * N_PHAL + p
    const float4* base = x + (size_t)chunk * F4_PER_CHUNK;
    const int t = threadIdx.x;

    float A = 0.f, Bm = 0.f, C = 0.f, D = 0.f, E = 0.f, F = 0.f, den = 0.f;

    #pragma unroll
    for (int it = 0; it < 2; ++it) {
        // ---- coalesced load: 2560 float4s, 10 per thread (LDG.128 full-line) ----
        #pragma unroll
        for (int k = 0; k < 10; ++k) {
            int idx = k * THREADS + t;
            tile[idx] = base[it * TILE_F4 + idx];
        }
        __syncthreads();

        // ---- deinterleave + accumulate: each thread does 2 groups of 4 positions ----
        #pragma unroll
        for (int gs = 0; gs < 2; ++gs) {
            int g = gs * THREADS + t;            // group-of-4 index within tile
            // 5 x LDS.128 at 80B lane stride: conflict-free
            float4 v0 = tile[g * 5 + 0];
            float4 v1 = tile[g * 5 + 1];
            float4 v2 = tile[g * 5 + 2];
            float4 v3 = tile[g * 5 + 3];
            float4 v4 = tile[g * 5 + 4];

            int pos0 = it * TILE_POS + g * 4;    // first global position of group
            float fi  = (float)(pos0 >> 6);      // row (same for all 4: 4 | 64)
            float fj0 = (float)(pos0 & 63);      // first column

            // p0: f0=v0.x f1=v0.y m=v0.z d0=v0.w d1=v1.x
            { float m = v0.z, am = fabsf(m), s = m * am;
              float t0 = s * v0.x, t1 = s * v0.y;
              A  = fmaf(t1, v0.w, A);  Bm = fmaf(t0, v0.w, Bm);
              C  = fmaf(t1, v1.x, C);  D  = fmaf(t0, v1.x, D);
              E  = fmaf(am, fi, E);    F  = fmaf(am, fj0, F);
              den += am; }
            // p1: f0=v1.y f1=v1.z m=v1.w d0=v2.x d1=v2.y
            { float m = v1.w, am = fabsf(m), s = m * am;
              float t0 = s * v1.y, t1 = s * v1.z;
              A  = fmaf(t1, v2.x, A);  Bm = fmaf(t0, v2.x, Bm);
              C  = fmaf(t1, v2.y, C);  D  = fmaf(t0, v2.y, D);
              E  = fmaf(am, fi, E);    F  = fmaf(am, fj0 + 1.f, F);
              den += am; }
            // p2: f0=v2.z f1=v2.w m=v3.x d0=v3.y d1=v3.z
            { float m = v3.x, am = fabsf(m), s = m * am;
              float t0 = s * v2.z, t1 = s * v2.w;
              A  = fmaf(t1, v3.y, A);  Bm = fmaf(t0, v3.y, Bm);
              C  = fmaf(t1, v3.z, C);  D  = fmaf(t0, v3.z, D);
              E  = fmaf(am, fi, E);    F  = fmaf(am, fj0 + 2.f, F);
              den += am; }
            // p3: f0=v3.w f1=v4.x m=v4.y d0=v4.z d1=v4.w
            { float m = v4.y, am = fabsf(m), s = m * am;
              float t0 = s * v3.w, t1 = s * v4.x;
              A  = fmaf(t1, v4.z, A);  Bm = fmaf(t0, v4.z, Bm);
              C  = fmaf(t1, v4.w, C);  D  = fmaf(t0, v4.w, D);
              E  = fmaf(am, fi, E);    F  = fmaf(am, fj0 + 3.f, F);
              den += am; }
        }
        __syncthreads();   // tile reused next iteration
    }

    // ---- block reduction of 7 accumulators ----
    A = warp_red(A);  Bm = warp_red(Bm); C = warp_red(C); D = warp_red(D);
    E = warp_red(E);  F  = warp_red(F);  den = warp_red(den);

    int wid = t >> 5, lane = t & 31;
    if (lane == 0) {
        red[wid][0] = A;  red[wid][1] = Bm; red[wid][2] = C;
        red[wid][3] = D;  red[wid][4] = E;  red[wid][5] = F;
        red[wid][6] = den;
    }
    __syncthreads();

    if (t == 0) {
        float a = 0.f, b = 0.f, c = 0.f, d = 0.f, e = 0.f, f = 0.f, dn = 0.f;
        #pragma unroll
        for (int w = 0; w < 8; ++w) {
            a += red[w][0]; b += red[w][1]; c += red[w][2];
            d += red[w][3]; e += red[w][4]; f += red[w][5];
            dn += red[w][6];
        }
        float inv = 1.f / ((dn == 0.f) ? 1.f : dn);
        float* o = scratch + (size_t)chunk * 5;
        o[0] = (a + e) * inv;   // vf0
        o[1] = (f - b) * inv;   // vf1
        o[2] = (e - c) * inv;   // vs0
        o[3] = (d + f) * inv;   // vs1
        o[4] = dn;

        __threadfence();        // scratch visible before counter bump
        unsigned int old = atomicAdd(&g_count, 1u);
        s_last = (old == gridDim.x - 1u) ? 1 : 0;
    }
    __syncthreads();

    // ---- last block assembles the (B, 21, 2) output (replaces 2nd launch) ----
    if (s_last) {
        if (t == 0) g_count = 0;          // reset for next graph replay
        __threadfence();
        const int B = total_chunks / N_PHAL;
        const int total = B * 42;
        for (int o = t; o < total; o += THREADS) {
            int c = o & 1;
            int r = (o >> 1) % 21;
            int b = o / 42;
            const float* sp = scratch + (size_t)b * N_PHAL * 5;

            float val;
            if (r == 0) {
                float acc = 0.f;
                #pragma unroll
                for (int k = 0; k < 5; ++k) {
                    int p = 4 * k;
                    float dn = __ldcg(sp + p * 5 + 4);
                    float vf = __ldcg(sp + p * 5 + c);
                    acc += (dn != 0.f) ? vf : 0.f;
                }
                val = acc * 0.2f;
            } else {
                int q  = r;                  // 1..20
                int iq = (q - 1) >> 2;
                int pq = 8 * iq + 4 - q;     // 4*iq + j_q
                int jq = pq - 4 * iq;
                int pn = min(pq + 1, N_PHAL - 1);
                float vs = __ldcg(sp + pq * 5 + 2 + c);
                if (jq == 3) val = vs;
                else         val = 0.5f * (vs + __ldcg(sp + pn * 5 + c));
            }
            out[o] = val;
        }
    }
}

extern "C" void kernel_launch(void* const* d_in, const int* in_sizes, int n_in,
                              void* d_out, int out_size)
{
    const float4* x = (const float4*)d_in[0];
    float* out = (float*)d_out;
    int B = in_sizes[0] / (N_PHAL * RES * RES * 5);   // 256
    int total_chunks = B * N_PHAL;                    // 5120

    float* scratch;
    cudaGetSymbolAddress((void**)&scratch, g_scratch);

    fused_kernel<<<total_chunks, THREADS>>>(x, scratch, out, total_chunks);
}

// round 13
// speedup vs baseline: 1.0583x; 1.0583x over previous
#include <cuda_runtime.h>
#include <cstdint>

#define RES      64
#define N_PHAL   20
#define MAX_B    256

constexpr int POS_PER_CHUNK = RES * RES;             // 4096 positions per (b,p)
constexpr int F4_PER_CHUNK  = POS_PER_CHUNK * 5 / 4; // 5120 float4s per chunk
constexpr int TILE_POS      = 2048;                  // positions per smem tile
constexpr int TILE_F4       = TILE_POS * 5 / 4;      // 2560 float4s = 40 KB
constexpr int THREADS       = 256;

// Scratch: per (b,p): vf0, vf1, vs0, vs1, den
__device__ float        g_scratch[MAX_B * N_PHAL * 5];
__device__ unsigned int g_count = 0;

__device__ __forceinline__ float warp_red(float v) {
    #pragma unroll
    for (int o = 16; o > 0; o >>= 1)
        v += __shfl_down_sync(0xffffffffu, v, o);
    return v;
}

// Release-ordered counter bump: orders this thread's prior global stores into
// L2 before the atomic commits. Crucially does NOT emit MEMBAR.ALL.GPU /
// CCTL.IVALL (no L1D flush) — that flush is what cost R11/R12 ~16 us.
__device__ __forceinline__ unsigned int atom_add_release(unsigned int* p,
                                                         unsigned int v) {
    unsigned int old;
    asm volatile("atom.release.gpu.add.u32 %0, [%1], %2;"
                 : "=r"(old) : "l"(p), "r"(v) : "memory");
    return old;
}

// One block per (b, phal) chunk: stream 80 KB through SMEM, reduce 7 sums.
// Hot body is byte-identical to the fastest measured engine (R2).
__global__ __launch_bounds__(THREADS) void fused_kernel(
    const float4* __restrict__ x, float* __restrict__ scratch,
    float* __restrict__ out, int total_chunks)
{
    __shared__ float4 tile[TILE_F4];     // 40 KB
    __shared__ float  red[8][7];
    __shared__ int    s_last;

    const int chunk = blockIdx.x;        // b * N_PHAL + p
    const float4* base = x + (size_t)chunk * F4_PER_CHUNK;
    const int t = threadIdx.x;

    float A = 0.f, Bm = 0.f, C = 0.f, D = 0.f, E = 0.f, F = 0.f, den = 0.f;

    #pragma unroll
    for (int it = 0; it < 2; ++it) {
        // ---- coalesced load: 2560 float4s, 10 per thread (LDG.128 full-line) ----
        #pragma unroll
        for (int k = 0; k < 10; ++k) {
            int idx = k * THREADS + t;
            tile[idx] = base[it * TILE_F4 + idx];
        }
        __syncthreads();

        // ---- deinterleave + accumulate: each thread does 2 groups of 4 positions ----
        #pragma unroll
        for (int gs = 0; gs < 2; ++gs) {
            int g = gs * THREADS + t;            // group-of-4 index within tile
            // 5 x LDS.128 at 80B lane stride: conflict-free
            float4 v0 = tile[g * 5 + 0];
            float4 v1 = tile[g * 5 + 1];
            float4 v2 = tile[g * 5 + 2];
            float4 v3 = tile[g * 5 + 3];
            float4 v4 = tile[g * 5 + 4];

            int pos0 = it * TILE_POS + g * 4;    // first global position of group
            float fi  = (float)(pos0 >> 6);      // row (same for all 4: 4 | 64)
            float fj0 = (float)(pos0 & 63);      // first column

            // p0: f0=v0.x f1=v0.y m=v0.z d0=v0.w d1=v1.x
            { float m = v0.z, am = fabsf(m), s = m * am;
              float t0 = s * v0.x, t1 = s * v0.y;
              A  = fmaf(t1, v0.w, A);  Bm = fmaf(t0, v0.w, Bm);
              C  = fmaf(t1, v1.x, C);  D  = fmaf(t0, v1.x, D);
              E  = fmaf(am, fi, E);    F  = fmaf(am, fj0, F);
              den += am; }
            // p1: f0=v1.y f1=v1.z m=v1.w d0=v2.x d1=v2.y
            { float m = v1.w, am = fabsf(m), s = m * am;
              float t0 = s * v1.y, t1 = s * v1.z;
              A  = fmaf(t1, v2.x, A);  Bm = fmaf(t0, v2.x, Bm);
              C  = fmaf(t1, v2.y, C);  D  = fmaf(t0, v2.y, D);
              E  = fmaf(am, fi, E);    F  = fmaf(am, fj0 + 1.f, F);
              den += am; }
            // p2: f0=v2.z f1=v2.w m=v3.x d0=v3.y d1=v3.z
            { float m = v3.x, am = fabsf(m), s = m * am;
              float t0 = s * v2.z, t1 = s * v2.w;
              A  = fmaf(t1, v3.y, A);  Bm = fmaf(t0, v3.y, Bm);
              C  = fmaf(t1, v3.z, C);  D  = fmaf(t0, v3.z, D);
              E  = fmaf(am, fi, E);    F  = fmaf(am, fj0 + 2.f, F);
              den += am; }
            // p3: f0=v3.w f1=v4.x m=v4.y d0=v4.z d1=v4.w
            { float m = v4.y, am = fabsf(m), s = m * am;
              float t0 = s * v3.w, t1 = s * v4.x;
              A  = fmaf(t1, v4.z, A);  Bm = fmaf(t0, v4.z, Bm);
              C  = fmaf(t1, v4.w, C);  D  = fmaf(t0, v4.w, D);
              E  = fmaf(am, fi, E);    F  = fmaf(am, fj0 + 3.f, F);
              den += am; }
        }
        __syncthreads();   // tile reused next iteration
    }

    // ---- block reduction of 7 accumulators ----
    A = warp_red(A);  Bm = warp_red(Bm); C = warp_red(C); D = warp_red(D);
    E = warp_red(E);  F  = warp_red(F);  den = warp_red(den);

    int wid = t >> 5, lane = t & 31;
    if (lane == 0) {
        red[wid][0] = A;  red[wid][1] = Bm; red[wid][2] = C;
        red[wid][3] = D;  red[wid][4] = E;  red[wid][5] = F;
        red[wid][6] = den;
    }
    __syncthreads();

    if (t == 0) {
        float a = 0.f, b = 0.f, c = 0.f, d = 0.f, e = 0.f, f = 0.f, dn = 0.f;
        #pragma unroll
        for (int w = 0; w < 8; ++w) {
            a += red[w][0]; b += red[w][1]; c += red[w][2];
            d += red[w][3]; e += red[w][4]; f += red[w][5];
            dn += red[w][6];
        }
        float inv = 1.f / ((dn == 0.f) ? 1.f : dn);
        float* o = scratch + (size_t)chunk * 5;
        o[0] = (a + e) * inv;   // vf0
        o[1] = (f - b) * inv;   // vf1
        o[2] = (e - c) * inv;   // vs0
        o[3] = (d + f) * inv;   // vs1
        o[4] = dn;

        // release atomic: scratch stores ordered into L2, NO L1 flush
        unsigned int old = atom_add_release(&g_count, 1u);
        s_last = (old == gridDim.x - 1u) ? 1 : 0;
    }
    __syncthreads();

    // ---- last block assembles the (B, 21, 2) output (replaces 2nd launch) ----
    // __ldcg reads hit L2, the coherence point every producer released into.
    if (s_last) {
        if (t == 0) g_count = 0;          // reset for next graph replay
        const int B = total_chunks / N_PHAL;
        const int total = B * 42;
        for (int o = t; o < total; o += THREADS) {
            int c = o & 1;
            int r = (o >> 1) % 21;
            int b = o / 42;
            const float* sp = scratch + (size_t)b * N_PHAL * 5;

            float val;
            if (r == 0) {
                float acc = 0.f;
                #pragma unroll
                for (int k = 0; k < 5; ++k) {
                    int p = 4 * k;
                    float dn = __ldcg(sp + p * 5 + 4);
                    float vf = __ldcg(sp + p * 5 + c);
                    acc += (dn != 0.f) ? vf : 0.f;
                }
                val = acc * 0.2f;
            } else {
                int q  = r;                  // 1..20
                int iq = (q - 1) >> 2;
                int pq = 8 * iq + 4 - q;     // 4*iq + j_q
                int jq = pq - 4 * iq;
                int pn = min(pq + 1, N_PHAL - 1);
                float vs = __ldcg(sp + pq * 5 + 2 + c);
                if (jq == 3) val = vs;
                else         val = 0.5f * (vs + __ldcg(sp + pn * 5 + c));
            }
            out[o] = val;
        }
    }
}

extern "C" void kernel_launch(void* const* d_in, const int* in_sizes, int n_in,
                              void* d_out, int out_size)
{
    const float4* x = (const float4*)d_in[0];
    float* out = (float*)d_out;
    int B = in_sizes[0] / (N_PHAL * RES * RES * 5);   // 256
    int total_chunks = B * N_PHAL;                    // 5120

    float* scratch;
    cudaGetSymbolAddress((void**)&scratch, g_scratch);

    fused_kernel<<<total_chunks, THREADS>>>(x, scratch, out, total_chunks);
}

// round 14
// speedup vs baseline: 1.4637x; 1.3831x over previous
#include <cuda_runtime.h>
#include <cstdint>

#define RES      64
#define N_PHAL   20
#define MAX_B    256

constexpr int POS_PER_CHUNK = RES * RES;             // 4096 positions per (b,p)
constexpr int F4_PER_CHUNK  = POS_PER_CHUNK * 5 / 4; // 5120 float4s per chunk
constexpr int TILE_POS      = 2048;                  // positions per smem tile
constexpr int TILE_F4       = TILE_POS * 5 / 4;      // 2560 float4s = 40 KB
constexpr int THREADS       = 256;

// Scratch: per (b,p): vf0, vf1, vs0, vs1, den
__device__ float g_scratch[MAX_B * N_PHAL * 5];

__device__ __forceinline__ float warp_red(float v) {
    #pragma unroll
    for (int o = 16; o > 0; o >>= 1)
        v += __shfl_down_sync(0xffffffffu, v, o);
    return v;
}

// One block per (b, phal) chunk: stream 80 KB through SMEM, reduce 7 sums.
// Identical to the best-measured engine (R2) except loads use __ldcs:
// LDG.E.128.CS = L1 bypass + L2 evict-first, so the one-shot 419 MB stream
// stops thrashing the 126 MB L2 with dead lines.
__global__ __launch_bounds__(THREADS) void reduce_kernel(
    const float4* __restrict__ x, float* __restrict__ scratch)
{
    __shared__ float4 tile[TILE_F4];     // 40 KB
    __shared__ float  red[8][7];

    const int chunk = blockIdx.x;        // b * N_PHAL + p
    const float4* base = x + (size_t)chunk * F4_PER_CHUNK;
    const int t = threadIdx.x;

    float A = 0.f, Bm = 0.f, C = 0.f, D = 0.f, E = 0.f, F = 0.f, den = 0.f;

    #pragma unroll
    for (int it = 0; it < 2; ++it) {
        // ---- coalesced streaming load: 2560 float4s, 10 per thread ----
        #pragma unroll
        for (int k = 0; k < 10; ++k) {
            int idx = k * THREADS + t;
            tile[idx] = __ldcs(base + it * TILE_F4 + idx);   // evict-first
        }
        __syncthreads();

        // ---- deinterleave + accumulate: each thread does 2 groups of 4 positions ----
        #pragma unroll
        for (int gs = 0; gs < 2; ++gs) {
            int g = gs * THREADS + t;            // group-of-4 index within tile
            // 5 x LDS.128 at 80B lane stride: conflict-free
            float4 v0 = tile[g * 5 + 0];
            float4 v1 = tile[g * 5 + 1];
            float4 v2 = tile[g * 5 + 2];
            float4 v3 = tile[g * 5 + 3];
            float4 v4 = tile[g * 5 + 4];

            int pos0 = it * TILE_POS + g * 4;    // first global position of group
            float fi  = (float)(pos0 >> 6);      // row (same for all 4: 4 | 64)
            float fj0 = (float)(pos0 & 63);      // first column

            // p0: f0=v0.x f1=v0.y m=v0.z d0=v0.w d1=v1.x
            { float m = v0.z, am = fabsf(m), s = m * am;
              float t0 = s * v0.x, t1 = s * v0.y;
              A  = fmaf(t1, v0.w, A);  Bm = fmaf(t0, v0.w, Bm);
              C  = fmaf(t1, v1.x, C);  D  = fmaf(t0, v1.x, D);
              E  = fmaf(am, fi, E);    F  = fmaf(am, fj0, F);
              den += am; }
            // p1: f0=v1.y f1=v1.z m=v1.w d0=v2.x d1=v2.y
            { float m = v1.w, am = fabsf(m), s = m * am;
              float t0 = s * v1.y, t1 = s * v1.z;
              A  = fmaf(t1, v2.x, A);  Bm = fmaf(t0, v2.x, Bm);
              C  = fmaf(t1, v2.y, C);  D  = fmaf(t0, v2.y, D);
              E  = fmaf(am, fi, E);    F  = fmaf(am, fj0 + 1.f, F);
              den += am; }
            // p2: f0=v2.z f1=v2.w m=v3.x d0=v3.y d1=v3.z
            { float m = v3.x, am = fabsf(m), s = m * am;
              float t0 = s * v2.z, t1 = s * v2.w;
              A  = fmaf(t1, v3.y, A);  Bm = fmaf(t0, v3.y, Bm);
              C  = fmaf(t1, v3.z, C);  D  = fmaf(t0, v3.z, D);
              E  = fmaf(am, fi, E);    F  = fmaf(am, fj0 + 2.f, F);
              den += am; }
            // p3: f0=v3.w f1=v4.x m=v4.y d0=v4.z d1=v4.w
            { float m = v4.y, am = fabsf(m), s = m * am;
              float t0 = s * v3.w, t1 = s * v4.x;
              A  = fmaf(t1, v4.z, A);  Bm = fmaf(t0, v4.z, Bm);
              C  = fmaf(t1, v4.w, C);  D  = fmaf(t0, v4.w, D);
              E  = fmaf(am, fi, E);    F  = fmaf(am, fj0 + 3.f, F);
              den += am; }
        }
        __syncthreads();   // tile reused next iteration
    }

    // ---- block reduction of 7 accumulators ----
    A = warp_red(A);  Bm = warp_red(Bm); C = warp_red(C); D = warp_red(D);
    E = warp_red(E);  F  = warp_red(F);  den = warp_red(den);

    int wid = t >> 5, lane = t & 31;
    if (lane == 0) {
        red[wid][0] = A;  red[wid][1] = Bm; red[wid][2] = C;
        red[wid][3] = D;  red[wid][4] = E;  red[wid][5] = F;
        red[wid][6] = den;
    }
    __syncthreads();

    if (t == 0) {
        float a = 0.f, b = 0.f, c = 0.f, d = 0.f, e = 0.f, f = 0.f, dn = 0.f;
        #pragma unroll
        for (int w = 0; w < 8; ++w) {
            a += red[w][0]; b += red[w][1]; c += red[w][2];
            d += red[w][3]; e += red[w][4]; f += red[w][5];
            dn += red[w][6];
        }
        float inv = 1.f / ((dn == 0.f) ? 1.f : dn);
        float* o = scratch + (size_t)chunk * 5;
        o[0] = (a + e) * inv;   // vf0
        o[1] = (f - b) * inv;   // vf1
        o[2] = (e - c) * inv;   // vs0
        o[3] = (d + f) * inv;   // vs1
        o[4] = dn;
    }
}

// Assemble (B, 21, 2) keypoints from per-(b,p) vf/vs/den.
__global__ void finalize_kernel(const float* __restrict__ scratch,
                                float* __restrict__ out, int total)
{
    int o = blockIdx.x * blockDim.x + threadIdx.x;
    if (o >= total) return;
    int c = o & 1;
    int r = (o >> 1) % 21;
    int b = o / 42;
    const float* s = scratch + (size_t)b * N_PHAL * 5;

    float val;
    if (r == 0) {
        float acc = 0.f;
        #pragma unroll
        for (int k = 0; k < 5; ++k) {
            int p = 4 * k;
            float dn = s[p * 5 + 4];
            float vf = s[p * 5 + c];
            acc += (dn != 0.f) ? vf : 0.f;
        }
        val = acc * 0.2f;
    } else {
        int q  = r;                 // 1..20
        int iq = (q - 1) >> 2;
        int pq = 8 * iq + 4 - q;    // = 4*iq + j_q
        int jq = pq - 4 * iq;
        int pn = min(pq + 1, N_PHAL - 1);
        float vs = s[pq * 5 + 2 + c];
        if (jq == 3) val = vs;                              // tip
        else         val = 0.5f * (vs + s[pn * 5 + c]);
    }
    out[o] = val;
}

extern "C" void kernel_launch(void* const* d_in, const int* in_sizes, int n_in,
                              void* d_out, int out_size)
{
    const float4* x = (const float4*)d_in[0];
    float* out = (float*)d_out;
    int B = in_sizes[0] / (N_PHAL * RES * RES * 5);   // 256

    float* scratch;
    cudaGetSymbolAddress((void**)&scratch, g_scratch);

    reduce_kernel<<<B * N_PHAL, THREADS>>>(x, scratch);

    int total = B * 21 * 2;
    finalize_kernel<<<(total + 255) / 256, 256>>>(scratch, out, total);
}

// round 15
// speedup vs baseline: 1.4945x; 1.0210x over previous
#include <cuda_runtime.h>
#include <cstdint>

#define RES      64
#define N_PHAL   20
#define MAX_B    256

constexpr int POS_PER_CHUNK = RES * RES;             // 4096 positions per (b,p)
constexpr int F4_PER_CHUNK  = POS_PER_CHUNK * 5 / 4; // 5120 float4s per chunk
constexpr int TILE_POS      = 2048;                  // positions per smem tile
constexpr int TILE_F4       = TILE_POS * 5 / 4;      // 2560 float4s = 40 KB
constexpr int THREADS       = 256;

// Scratch: per (b,p): vf0, vf1, vs0, vs1, den
__device__ float g_scratch[MAX_B * N_PHAL * 5];

__device__ __forceinline__ float warp_red(float v) {
    #pragma unroll
    for (int o = 16; o > 0; o >>= 1)
        v += __shfl_down_sync(0xffffffffu, v, o);
    return v;
}

// One block per (b, phal) chunk: stream 80 KB through SMEM, reduce 7 sums.
// PROTECTED ENGINE (R14, 6.3 TB/s): R2 schedule + __ldcs evict-first loads.
__global__ __launch_bounds__(THREADS) void reduce_kernel(
    const float4* __restrict__ x, float* __restrict__ scratch)
{
    __shared__ float4 tile[TILE_F4];     // 40 KB
    __shared__ float  red[8][7];

    const int chunk = blockIdx.x;        // b * N_PHAL + p
    const float4* base = x + (size_t)chunk * F4_PER_CHUNK;
    const int t = threadIdx.x;

    float A = 0.f, Bm = 0.f, C = 0.f, D = 0.f, E = 0.f, F = 0.f, den = 0.f;

    #pragma unroll
    for (int it = 0; it < 2; ++it) {
        // ---- coalesced streaming load: 2560 float4s, 10 per thread ----
        #pragma unroll
        for (int k = 0; k < 10; ++k) {
            int idx = k * THREADS + t;
            tile[idx] = __ldcs(base + it * TILE_F4 + idx);   // evict-first
        }
        __syncthreads();

        // ---- deinterleave + accumulate: each thread does 2 groups of 4 positions ----
        #pragma unroll
        for (int gs = 0; gs < 2; ++gs) {
            int g = gs * THREADS + t;            // group-of-4 index within tile
            // 5 x LDS.128 at 80B lane stride: conflict-free
            float4 v0 = tile[g * 5 + 0];
            float4 v1 = tile[g * 5 + 1];
            float4 v2 = tile[g * 5 + 2];
            float4 v3 = tile[g * 5 + 3];
            float4 v4 = tile[g * 5 + 4];

            int pos0 = it * TILE_POS + g * 4;    // first global position of group
            float fi  = (float)(pos0 >> 6);      // row (same for all 4: 4 | 64)
            float fj0 = (float)(pos0 & 63);      // first column

            // p0: f0=v0.x f1=v0.y m=v0.z d0=v0.w d1=v1.x
            { float m = v0.z, am = fabsf(m), s = m * am;
              float t0 = s * v0.x, t1 = s * v0.y;
              A  = fmaf(t1, v0.w, A);  Bm = fmaf(t0, v0.w, Bm);
              C  = fmaf(t1, v1.x, C);  D  = fmaf(t0, v1.x, D);
              E  = fmaf(am, fi, E);    F  = fmaf(am, fj0, F);
              den += am; }
            // p1: f0=v1.y f1=v1.z m=v1.w d0=v2.x d1=v2.y
            { float m = v1.w, am = fabsf(m), s = m * am;
              float t0 = s * v1.y, t1 = s * v1.z;
              A  = fmaf(t1, v2.x, A);  Bm = fmaf(t0, v2.x, Bm);
              C  = fmaf(t1, v2.y, C);  D  = fmaf(t0, v2.y, D);
              E  = fmaf(am, fi, E);    F  = fmaf(am, fj0 + 1.f, F);
              den += am; }
            // p2: f0=v2.z f1=v2.w m=v3.x d0=v3.y d1=v3.z
            { float m = v3.x, am = fabsf(m), s = m * am;
              float t0 = s * v2.z, t1 = s * v2.w;
              A  = fmaf(t1, v3.y, A);  Bm = fmaf(t0, v3.y, Bm);
              C  = fmaf(t1, v3.z, C);  D  = fmaf(t0, v3.z, D);
              E  = fmaf(am, fi, E);    F  = fmaf(am, fj0 + 2.f, F);
              den += am; }
            // p3: f0=v3.w f1=v4.x m=v4.y d0=v4.z d1=v4.w
            { float m = v4.y, am = fabsf(m), s = m * am;
              float t0 = s * v3.w, t1 = s * v4.x;
              A  = fmaf(t1, v4.z, A);  Bm = fmaf(t0, v4.z, Bm);
              C  = fmaf(t1, v4.w, C);  D  = fmaf(t0, v4.w, D);
              E  = fmaf(am, fi, E);    F  = fmaf(am, fj0 + 3.f, F);
              den += am; }
        }
        __syncthreads();   // tile reused next iteration
    }

    // ---- block reduction of 7 accumulators ----
    A = warp_red(A);  Bm = warp_red(Bm); C = warp_red(C); D = warp_red(D);
    E = warp_red(E);  F  = warp_red(F);  den = warp_red(den);

    int wid = t >> 5, lane = t & 31;
    if (lane == 0) {
        red[wid][0] = A;  red[wid][1] = Bm; red[wid][2] = C;
        red[wid][3] = D;  red[wid][4] = E;  red[wid][5] = F;
        red[wid][6] = den;
    }
    __syncthreads();

    if (t == 0) {
        float a = 0.f, b = 0.f, c = 0.f, d = 0.f, e = 0.f, f = 0.f, dn = 0.f;
        #pragma unroll
        for (int w = 0; w < 8; ++w) {
            a += red[w][0]; b += red[w][1]; c += red[w][2];
            d += red[w][3]; e += red[w][4]; f += red[w][5];
            dn += red[w][6];
        }
        float inv = 1.f / ((dn == 0.f) ? 1.f : dn);
        float* o = scratch + (size_t)chunk * 5;
        o[0] = (a + e) * inv;   // vf0
        o[1] = (f - b) * inv;   // vf1
        o[2] = (e - c) * inv;   // vs0
        o[3] = (d + f) * inv;   // vs1
        o[4] = dn;
    }
}

// Assemble (B, 21, 2) keypoints. Launched with PDL: CTAs go resident while
// reduce_kernel is still streaming, park at the grid-dependency sync, and run
// the moment the reduce completes — launch latency fully hidden.
__global__ void finalize_kernel(const float* __restrict__ scratch,
                                float* __restrict__ out, int total)
{
#if __CUDA_ARCH__ >= 900
    cudaGridDependencySynchronize();     // wait for reduce_kernel completion
#endif
    int o = blockIdx.x * blockDim.x + threadIdx.x;
    if (o >= total) return;
    int c = o & 1;
    int r = (o >> 1) % 21;
    int b = o / 42;
    const float* s = scratch + (size_t)b * N_PHAL * 5;

    float val;
    if (r == 0) {
        float acc = 0.f;
        #pragma unroll
        for (int k = 0; k < 5; ++k) {
            int p = 4 * k;
            float dn = s[p * 5 + 4];
            float vf = s[p * 5 + c];
            acc += (dn != 0.f) ? vf : 0.f;
        }
        val = acc * 0.2f;
    } else {
        int q  = r;                 // 1..20
        int iq = (q - 1) >> 2;
        int pq = 8 * iq + 4 - q;    // = 4*iq + j_q
        int jq = pq - 4 * iq;
        int pn = min(pq + 1, N_PHAL - 1);
        float vs = s[pq * 5 + 2 + c];
        if (jq == 3) val = vs;                              // tip
        else         val = 0.5f * (vs + s[pn * 5 + c]);
    }
    out[o] = val;
}

extern "C" void kernel_launch(void* const* d_in, const int* in_sizes, int n_in,
                              void* d_out, int out_size)
{
    const float4* x = (const float4*)d_in[0];
    float* out = (float*)d_out;
    int B = in_sizes[0] / (N_PHAL * RES * RES * 5);   // 256

    float* scratch;
    cudaGetSymbolAddress((void**)&scratch, g_scratch);

    reduce_kernel<<<B * N_PHAL, THREADS>>>(x, scratch);

    int total = B * 21 * 2;

    // PDL launch: finalize overlaps the reduce's tail; its grid-dependency
    // sync releases when reduce_kernel's completion trigger fires.
    cudaLaunchConfig_t cfg = {};
    cfg.gridDim  = dim3((total + 255) / 256, 1, 1);
    cfg.blockDim = dim3(256, 1, 1);
    cfg.dynamicSmemBytes = 0;
    cfg.stream = 0;
    cudaLaunchAttribute attr[1];
    attr[0].id = cudaLaunchAttributeProgrammaticStreamSerialization;
    attr[0].val.programmaticStreamSerializationAllowed = 1;
    cfg.attrs = attr;
    cfg.numAttrs = 1;
    cudaLaunchKernelEx(&cfg, finalize_kernel, (const float*)scratch, out, total);
}